// round 3
// baseline (speedup 1.0000x reference)
#include <cuda_runtime.h>
#include <cuda_bf16.h>
#include <math.h>

// ---------------- problem constants ----------------
#define BATCH 256
#define SIG_LEN 2048
#define NCH 3
#define O1 128
#define P1 1022          // conv1(k3) -> 2046, pool k3 s2 -> 1022
#define O2 64
#define P2 339           // conv2(k5) -> 1018, pool k3 s3 -> 339
#define O3 64
#define P3 168           // conv3(k3) -> 337, pool k3 s2 -> 168
#define FC_IN 10752      // 64*168
#define EPS_BN 1e-5f

// ---------------- device scratch (no allocations allowed) ----------------
__device__ float g_h1[(size_t)BATCH * O1 * P1];   // 134 MB
__device__ float g_h2[(size_t)BATCH * O2 * P2];   // 22 MB
__device__ float g_h3[(size_t)BATCH * O3 * P3];   // 11 MB
__device__ float g_fc1[BATCH * 48];
__device__ float g_A[BATCH * 12];

// ============================================================
// Kernel 1: conv1(k3) + BN + maxpool(3,2) + ReLU  -> g_h1
// thread per (b, pooled j), loops all 128 output channels
// ============================================================
__global__ void k_conv1(const float* __restrict__ x, const float* __restrict__ w,
                        const float* __restrict__ cb, const float* __restrict__ g,
                        const float* __restrict__ be, const float* __restrict__ m,
                        const float* __restrict__ v) {
    __shared__ float ws[O1 * 9];
    __shared__ float Ss[O1], Ts[O1];
    int b = blockIdx.y;
    int tid = threadIdx.x;
    for (int i = tid; i < O1 * 9; i += 128) ws[i] = w[i];
    if (tid < O1) {
        float s = g[tid] / sqrtf(v[tid] + EPS_BN);
        Ss[tid] = s;
        Ts[tid] = (cb[tid] - m[tid]) * s + be[tid];
    }
    __syncthreads();
    int j = blockIdx.x * 128 + tid;
    if (j >= P1) return;

    const float* xb = x + (size_t)b * NCH * SIG_LEN;
    float xv[3][5];
#pragma unroll
    for (int c = 0; c < 3; c++)
#pragma unroll
        for (int k = 0; k < 5; k++)
            xv[c][k] = xb[c * SIG_LEN + 2 * j + k];

    float* h1 = g_h1 + (size_t)b * O1 * P1;
#pragma unroll 4
    for (int o = 0; o < O1; o++) {
        const float* wo = ws + o * 9;
        float y0 = 0.f, y1 = 0.f, y2 = 0.f;
#pragma unroll
        for (int c = 0; c < 3; c++) {
#pragma unroll
            for (int k = 0; k < 3; k++) {
                float wv = wo[c * 3 + k];
                y0 += xv[c][k] * wv;
                y1 += xv[c][k + 1] * wv;
                y2 += xv[c][k + 2] * wv;
            }
        }
        float S = Ss[o], T = Ts[o];
        float r = fmaxf(fmaxf(y0 * S + T, y1 * S + T), y2 * S + T);
        h1[(size_t)o * P1 + j] = fmaxf(r, 0.f);
    }
}

// ============================================================
// Kernel 2: conv2(k5, 128ch) + BN + maxpool(3,3) + ReLU -> g_h2
// Block: (b, 32 pooled outputs). 256 thr = 64 o x 4 jgroups (8 pooled each).
// c chunked by 16; h1 tile + transposed weights in smem; register-window inner.
// ============================================================
#define CC2 16
__global__ void k_conv2(const float* __restrict__ w, const float* __restrict__ cb,
                        const float* __restrict__ g, const float* __restrict__ be,
                        const float* __restrict__ m, const float* __restrict__ v) {
    __shared__ float hs[CC2][100];
    __shared__ float ws[CC2 * 5][65];
    __shared__ float Ss[O2], Ts[O2];
    int b = blockIdx.y;
    int j0 = blockIdx.x * 32;
    int tid = threadIdx.x;
    if (tid < O2) {
        float s = g[tid] / sqrtf(v[tid] + EPS_BN);
        Ss[tid] = s;
        Ts[tid] = (cb[tid] - m[tid]) * s + be[tid];
    }
    int o = tid & 63;
    int jg = tid >> 6;
    int lb = jg * 24;

    float acc[24];
#pragma unroll
    for (int i = 0; i < 24; i++) acc[i] = 0.f;

    const float* h1b = g_h1 + (size_t)b * O1 * P1;
    int gbase = 3 * j0;

    for (int c0 = 0; c0 < O1; c0 += CC2) {
        __syncthreads();
        for (int idx = tid; idx < CC2 * 100; idx += 256) {
            int cc = idx / 100, p = idx - cc * 100;
            int gp = gbase + p;
            hs[cc][p] = (gp < P1) ? h1b[(size_t)(c0 + cc) * P1 + gp] : 0.f;
        }
        for (int idx = tid; idx < 64 * 80; idx += 256) {
            int oo = idx / 80, r = idx - oo * 80;
            ws[r][oo] = w[oo * 640 + c0 * 5 + r];
        }
        __syncthreads();
#pragma unroll 1
        for (int cc = 0; cc < CC2; cc++) {
            float wr[5];
#pragma unroll
            for (int k = 0; k < 5; k++) wr[k] = ws[cc * 5 + k][o];
            float h[28];
#pragma unroll
            for (int p = 0; p < 28; p++) h[p] = hs[cc][lb + p];
#pragma unroll
            for (int l = 0; l < 24; l++) {
                float s = acc[l];
#pragma unroll
                for (int k = 0; k < 5; k++) s += h[l + k] * wr[k];
                acc[l] = s;
            }
        }
    }
    float S = Ss[o], T = Ts[o];
    float* h2b = g_h2 + (size_t)b * O2 * P2;
#pragma unroll
    for (int jj = 0; jj < 8; jj++) {
        int jglob = j0 + jg * 8 + jj;
        if (jglob < P2) {
            float a0 = acc[3 * jj] * S + T;
            float a1 = acc[3 * jj + 1] * S + T;
            float a2 = acc[3 * jj + 2] * S + T;
            h2b[o * P2 + jglob] = fmaxf(fmaxf(fmaxf(a0, a1), a2), 0.f);
        }
    }
}

// ============================================================
// Kernel 3: conv3(k3, 64ch) + BN + maxpool(3,2) + ReLU -> g_h3
// Block: (b, 24 pooled outputs). 256 thr = 64 o x 4 jgroups (6 pooled each).
// 168 = 7*24 exact, all indices in range (no guards needed).
// ============================================================
__global__ void k_conv3(const float* __restrict__ w, const float* __restrict__ cb,
                        const float* __restrict__ g, const float* __restrict__ be,
                        const float* __restrict__ m, const float* __restrict__ v) {
    __shared__ float hs[64][51];
    __shared__ float ws[96][65];
    __shared__ float Ss[O3], Ts[O3];
    int b = blockIdx.y;
    int j0 = blockIdx.x * 24;
    int tid = threadIdx.x;
    if (tid < O3) {
        float s = g[tid] / sqrtf(v[tid] + EPS_BN);
        Ss[tid] = s;
        Ts[tid] = (cb[tid] - m[tid]) * s + be[tid];
    }
    const float* h2b = g_h2 + (size_t)b * O2 * P2;
    for (int idx = tid; idx < 64 * 51; idx += 256) {
        int cc = idx / 51, p = idx - cc * 51;
        hs[cc][p] = h2b[cc * P2 + 2 * j0 + p];
    }
    int o = tid & 63;
    int jg = tid >> 6;
    int lb = jg * 12;

    float acc[13];
#pragma unroll
    for (int i = 0; i < 13; i++) acc[i] = 0.f;

    for (int c0 = 0; c0 < 64; c0 += 32) {
        __syncthreads();
        for (int idx = tid; idx < 64 * 96; idx += 256) {
            int oo = idx / 96, r = idx - oo * 96;
            ws[r][oo] = w[oo * 192 + c0 * 3 + r];
        }
        __syncthreads();
#pragma unroll 1
        for (int cc = 0; cc < 32; cc++) {
            float wr[3];
#pragma unroll
            for (int k = 0; k < 3; k++) wr[k] = ws[cc * 3 + k][o];
            float h[15];
#pragma unroll
            for (int p = 0; p < 15; p++) h[p] = hs[c0 + cc][lb + p];
#pragma unroll
            for (int l = 0; l < 13; l++) {
                float s = acc[l];
#pragma unroll
                for (int k = 0; k < 3; k++) s += h[l + k] * wr[k];
                acc[l] = s;
            }
        }
    }
    float S = Ss[o], T = Ts[o];
    float* h3b = g_h3 + (size_t)b * O3 * P3;
#pragma unroll
    for (int jj = 0; jj < 6; jj++) {
        int jglob = j0 + jg * 6 + jj;
        float a0 = acc[2 * jj] * S + T;
        float a1 = acc[2 * jj + 1] * S + T;
        float a2 = acc[2 * jj + 2] * S + T;
        h3b[o * P3 + jglob] = fmaxf(fmaxf(fmaxf(a0, a1), a2), 0.f);
    }
}

// ============================================================
// Kernel 4: fc1 (10752 -> 48) + ReLU. Block per batch, warp per 6 outputs.
// ============================================================
__global__ void k_fc1(const float* __restrict__ w, const float* __restrict__ bias) {
    int b = blockIdx.x;
    const float* h = g_h3 + (size_t)b * FC_IN;
    int warp = threadIdx.x >> 5, lane = threadIdx.x & 31;
#pragma unroll 1
    for (int oi = 0; oi < 6; oi++) {
        int o = warp + oi * 8;
        const float* wo = w + (size_t)o * FC_IN;
        float s = 0.f;
        for (int i = lane; i < FC_IN; i += 32) s += h[i] * wo[i];
#pragma unroll
        for (int off = 16; off; off >>= 1) s += __shfl_down_sync(0xffffffffu, s, off);
        if (lane == 0) g_fc1[b * 48 + o] = fmaxf(s + bias[o], 0.f);
    }
}

// ============================================================
// Kernel 5: fc2 -> fc3 -> fc4 -> tanh -> A = theta @ basis^T. One block, thread=b.
// ============================================================
__global__ void k_fchead(const float* __restrict__ w2, const float* __restrict__ b2,
                         const float* __restrict__ w3, const float* __restrict__ b3,
                         const float* __restrict__ w4, const float* __restrict__ b4,
                         const float* __restrict__ basis) {
    __shared__ float s2[32 * 48], sb2[32], s3[16 * 32], sb3[16], s4[5 * 16], sb4[5], sbas[60];
    int t = threadIdx.x;
    for (int i = t; i < 1536; i += 256) s2[i] = w2[i];
    for (int i = t; i < 512; i += 256) s3[i] = w3[i];
    if (t < 80) s4[t] = w4[t];
    if (t < 32) sb2[t] = b2[t];
    if (t < 16) sb3[t] = b3[t];
    if (t < 5)  sb4[t] = b4[t];
    if (t < 60) sbas[t] = basis[t];
    __syncthreads();
    int b = t;
    float x1[48];
#pragma unroll
    for (int i = 0; i < 48; i++) x1[i] = g_fc1[b * 48 + i];
    float x2[32];
#pragma unroll
    for (int o = 0; o < 32; o++) {
        float s = sb2[o];
#pragma unroll
        for (int i = 0; i < 48; i++) s += x1[i] * s2[o * 48 + i];
        x2[o] = fmaxf(s, 0.f);
    }
    float x3[16];
#pragma unroll
    for (int o = 0; o < 16; o++) {
        float s = sb3[o];
#pragma unroll
        for (int i = 0; i < 32; i++) s += x2[i] * s3[o * 32 + i];
        x3[o] = fmaxf(s, 0.f);
    }
    float th[5];
#pragma unroll
    for (int o = 0; o < 5; o++) {
        float s = sb4[o];
#pragma unroll
        for (int i = 0; i < 16; i++) s += x3[i] * s4[o * 16 + i];
        th[o] = tanhf(s);
    }
#pragma unroll
    for (int r = 0; r < 12; r++) {
        float s = 0.f;
#pragma unroll
        for (int jq = 0; jq < 5; jq++) s += th[jq] * sbas[r * 5 + jq];
        g_A[b * 12 + r] = s;
    }
}

// ============================================================
// Kernel 6: exact CPAB integration of the grid + linear interpolation of x.
// Thread per (b, output position). Mirrors the reference branch-for-branch.
// ============================================================
__global__ void k_warp(const float* __restrict__ x, float* __restrict__ out) {
    __shared__ float a_s[6], b_s[6];
    int b = blockIdx.y;
    if (threadIdx.x < 12) {
        float val = g_A[b * 12 + threadIdx.x];
        if (threadIdx.x & 1) b_s[threadIdx.x >> 1] = val;
        else                 a_s[threadIdx.x >> 1] = val;
    }
    __syncthreads();
    int i = blockIdx.x * 256 + threadIdx.x;

    float xt = (float)i * (1.0f / 2047.0f);
    float t = 1.0f;
#pragma unroll 1
    for (int it = 0; it < 7; it++) {          // NC + 1 iterations
        int c = (int)floorf(xt * 6.0f);
        c = max(0, min(c, 5));
        float a = a_s[c], bb = b_s[c];
        float vv = a * xt + bb;
        float xbn = (vv >= 0.f) ? (float)(c + 1) / 6.0f : (float)c / 6.0f;
        bool big = fabsf(a) > 1e-8f;
        float a_sv = big ? a : 1.0f;
        float z  = xt  + bb / a_sv;
        float zb = xbn + bb / a_sv;
        float zden = (fabsf(z) > 1e-12f) ? z : 1e-12f;
        float ratio = zb / zden;
        float t_exp = logf(fmaxf(ratio, 1e-12f)) / a_sv;
        float v_sv = (fabsf(vv) > 1e-12f) ? vv : 1.0f;
        float t_lin = (xbn - xt) / v_sv;
        float thit = big ? t_exp : t_lin;
        bool valid = (fabsf(vv) > 1e-12f) && (thit > 0.f) && ((big ? ratio : 1.0f) > 0.f);
        if (!valid) thit = INFINITY;
        float tau = fminf(t, thit);
        float xn = big ? (z * expf(a * tau) - (z - xt)) : (xt + bb * tau);
        bool hit = (thit <= t);
        float nudge = (vv >= 0.f) ? 1e-6f : -1e-6f;
        xt = hit ? (xbn + nudge) : xn;
        xt = fminf(fmaxf(xt, 0.f), 1.f);
        t = fmaxf(t - tau, 0.f);
    }
    // linear interp of x[b, c, :] at position xt
    float p = fminf(fmaxf(xt, 0.f), 1.f) * 2047.0f;
    int x0 = (int)floorf(p);
    x0 = max(0, min(x0, 2046));
    float wgt = p - (float)x0;
    const float* xb = x + (size_t)b * NCH * SIG_LEN;
    float* ob = out + (size_t)b * NCH * SIG_LEN;
#pragma unroll
    for (int cch = 0; cch < NCH; cch++) {
        float d0 = xb[cch * SIG_LEN + x0];
        float d1 = xb[cch * SIG_LEN + x0 + 1];
        ob[cch * SIG_LEN + i] = d0 * (1.0f - wgt) + d1 * wgt;
    }
}

// ============================================================
extern "C" void kernel_launch(void* const* d_in, const int* in_sizes, int n_in,
                              void* d_out, int out_size) {
    const float* x       = (const float*)d_in[0];
    const float* c1w     = (const float*)d_in[1];
    const float* c1b     = (const float*)d_in[2];
    const float* bn1g    = (const float*)d_in[3];
    const float* bn1b    = (const float*)d_in[4];
    const float* bn1m    = (const float*)d_in[5];
    const float* bn1v    = (const float*)d_in[6];
    const float* c2w     = (const float*)d_in[7];
    const float* c2b     = (const float*)d_in[8];
    const float* bn2g    = (const float*)d_in[9];
    const float* bn2b    = (const float*)d_in[10];
    const float* bn2m    = (const float*)d_in[11];
    const float* bn2v    = (const float*)d_in[12];
    const float* c3w     = (const float*)d_in[13];
    const float* c3b     = (const float*)d_in[14];
    const float* bn3g    = (const float*)d_in[15];
    const float* bn3b    = (const float*)d_in[16];
    const float* bn3m    = (const float*)d_in[17];
    const float* bn3v    = (const float*)d_in[18];
    const float* fc1w    = (const float*)d_in[19];
    const float* fc1b    = (const float*)d_in[20];
    const float* fc2w    = (const float*)d_in[21];
    const float* fc2b    = (const float*)d_in[22];
    const float* fc3w    = (const float*)d_in[23];
    const float* fc3b    = (const float*)d_in[24];
    const float* fc4w    = (const float*)d_in[25];
    const float* fc4b    = (const float*)d_in[26];
    const float* basis   = (const float*)d_in[27];
    float* out = (float*)d_out;

    k_conv1<<<dim3((P1 + 127) / 128, BATCH), 128>>>(x, c1w, c1b, bn1g, bn1b, bn1m, bn1v);
    k_conv2<<<dim3((P2 + 31) / 32, BATCH), 256>>>(c2w, c2b, bn2g, bn2b, bn2m, bn2v);
    k_conv3<<<dim3(P3 / 24, BATCH), 256>>>(c3w, c3b, bn3g, bn3b, bn3m, bn3v);
    k_fc1<<<BATCH, 256>>>(fc1w, fc1b);
    k_fchead<<<1, 256>>>(fc2w, fc2b, fc3w, fc3b, fc4w, fc4b, basis);
    k_warp<<<dim3(SIG_LEN / 256, BATCH), 256>>>(x, out);
}